// round 14
// baseline (speedup 1.0000x reference)
#include <cuda_runtime.h>
#include <cstdint>

#define N_ROWS  262144
#define DIM     256
#define CLUSTER 512
#define SLACK   1024
#define NPAIRS  (CLUSTER * (CLUSTER - 1) / 2)   // 130816
#define NTILES  136                             // 16*17/2 upper-tri 32x32 tiles
#define SCTAS   128
#define RPC     (N_ROWS / SCTAS)                // 2048
#define CPAD    32                              // 1 cursor per 128B line

// k_sums ring geometry
#define STG_ROWS 16
#define NSTAGE   4
#define ROW_B    (DIM * 4)                      // 1024 bytes per row
#define STG_B    (STG_ROWS * ROW_B)             // 16384
#define SIDX_CAP 768                            // >> max cluster count (~600)
#define OFF_BUF  0
#define OFF_SIDX (NSTAGE * STG_B)               // 65536
#define OFF_MBAR (OFF_SIDX + SIDX_CAP * 4)      // 68608
#define SMEM_DYN (OFF_MBAR + NSTAGE * 8)        // 68640

// ---- device scratch (zero-initialized at module load; the LAST k_pdist CTA
//      resets cursors/pair/done so each graph replay sees zeros) ----
__device__ int   d_cursor[CLUSTER * CPAD];         // padded: 1 line per counter
__device__ int   d_perm[CLUSTER * SLACK];          // 2 MB
__device__ float d_centers[CLUSTER * DIM];         // 512 KB (L2-resident)
__device__ float d_norms[CLUSTER];
__device__ float d_pair_sum;
__device__ int   d_done;

// ---------------------------------------------------------------------------
// PTX helpers
// ---------------------------------------------------------------------------
__device__ __forceinline__ uint32_t smem_u32(const void* p) {
    return (uint32_t)__cvta_generic_to_shared(p);
}
__device__ __forceinline__ void mbar_init(uint32_t a, uint32_t cnt) {
    asm volatile("mbarrier.init.shared.b64 [%0], %1;" :: "r"(a), "r"(cnt) : "memory");
}
__device__ __forceinline__ void mbar_expect_tx(uint32_t a, uint32_t bytes) {
    asm volatile("mbarrier.arrive.expect_tx.shared.b64 _, [%0], %1;"
                 :: "r"(a), "r"(bytes) : "memory");
}
__device__ __forceinline__ void mbar_wait(uint32_t a, uint32_t ph) {
    asm volatile(
        "{\n\t.reg .pred P;\n"
        "WAIT_%=:\n\t"
        "mbarrier.try_wait.parity.acquire.cta.shared::cta.b64 P, [%0], %1, 0x989680;\n\t"
        "@P bra.uni DONE_%=;\n\t"
        "bra.uni WAIT_%=;\n"
        "DONE_%=:\n\t}"
        :: "r"(a), "r"(ph) : "memory");
}
__device__ __forceinline__ void cp_bulk_1k(uint32_t dst, const float* src,
                                           uint32_t bytes, uint32_t bar) {
    asm volatile(
        "cp.async.bulk.shared::cluster.global.mbarrier::complete_tx::bytes "
        "[%0], [%1], %2, [%3];"
        :: "r"(dst), "l"(src), "r"(bytes), "r"(bar) : "memory");
}

// ---------------------------------------------------------------------------
// k_scatter: CTA-aggregated counting scatter (r10 version, measured 7.07us).
// ---------------------------------------------------------------------------
__global__ void __launch_bounds__(512) k_scatter(const int* __restrict__ label) {
    __shared__ int hist[CLUSTER];
    __shared__ int curs[CLUSTER];
    int t  = threadIdx.x;
    int r0 = blockIdx.x * RPC;

    hist[t] = 0;
    __syncthreads();

    int labs[4];
#pragma unroll
    for (int k = 0; k < 4; k++) {
        labs[k] = label[r0 + k * 512 + t];
        atomicAdd(&hist[labs[k]], 1);
    }
    __syncthreads();

    int h = hist[t];
    curs[t] = t * SLACK + ((h > 0) ? atomicAdd(&d_cursor[t * CPAD], h) : 0);
    __syncthreads();

#pragma unroll
    for (int k = 0; k < 4; k++) {
        int pos = atomicAdd(&curs[labs[k]], 1);
        d_perm[pos] = r0 + k * 512 + t;
    }
}

// ---------------------------------------------------------------------------
// k_sums: one CTA per cluster, 256 threads. Rows fetched as WHOLE 1KB
// cp.async.bulk copies into a 4-stage x 16-row smem ring (mbarrier
// expect_tx completion) -> DRAM sees contiguous 1KB bursts instead of
// random 512B warp granules; 64KB in flight per CTA. Thread t consumes
// column t (conflict-free LDS.32). __syncthreads recycles ring slots.
// ---------------------------------------------------------------------------
__global__ void __launch_bounds__(256) k_sums(const float* __restrict__ matrix) {
    extern __shared__ __align__(16) char dyn[];
    float*    buf  = (float*)(dyn + OFF_BUF);          // [NSTAGE][16][256]
    int*      sidx = (int*)(dyn + OFF_SIDX);
    uint32_t  mb   = smem_u32(dyn + OFF_MBAR);
    uint32_t  bufb = smem_u32(dyn + OFF_BUF);
    __shared__ float partw[8];

    int c = blockIdx.x;
    int t = threadIdx.x;
    int cnt = d_cursor[c * CPAD];

    const int* __restrict__ p = d_perm + c * SLACK;
    for (int i = t; i < cnt; i += 256) sidx[i] = p[i];
    if (t < NSTAGE) mbar_init(mb + t * 8, 1);
    __syncthreads();

    int nst = (cnt + STG_ROWS - 1) / STG_ROWS;

    // prologue: fill the ring
    if (t == 0) {
        int pre = nst < NSTAGE ? nst : NSTAGE;
        for (int s = 0; s < pre; s++) {
            int m = min(STG_ROWS, cnt - s * STG_ROWS);
            uint32_t bar = mb + (s & (NSTAGE - 1)) * 8;
            mbar_expect_tx(bar, m * ROW_B);
            uint32_t dst = bufb + (s & (NSTAGE - 1)) * STG_B;
            for (int r = 0; r < m; r++)
                cp_bulk_1k(dst + r * ROW_B, matrix + (size_t)sidx[s * STG_ROWS + r] * DIM,
                           ROW_B, bar);
        }
    }

    float acc = 0.0f;
    for (int s = 0; s < nst; s++) {
        int slot = s & (NSTAGE - 1);
        mbar_wait(mb + slot * 8, (s >> 2) & 1);
        int lim = min(STG_ROWS, cnt - s * STG_ROWS);
        const float* B = buf + slot * (STG_ROWS * DIM);
        for (int r = 0; r < lim; r++)
            acc += B[r * DIM + t];
        __syncthreads();                       // slot drained by all threads
        int s2 = s + NSTAGE;
        if (t == 0 && s2 < nst) {
            int m = min(STG_ROWS, cnt - s2 * STG_ROWS);
            uint32_t bar = mb + slot * 8;
            mbar_expect_tx(bar, m * ROW_B);
            uint32_t dst = bufb + slot * STG_B;
            for (int r = 0; r < m; r++)
                cp_bulk_1k(dst + r * ROW_B, matrix + (size_t)sidx[s2 * STG_ROWS + r] * DIM,
                           ROW_B, bar);
        }
    }

    // center + norm
    float cen = acc / fmaxf((float)cnt, 1.0f);
    d_centers[c * DIM + t] = cen;

    float sq = cen * cen;
#pragma unroll
    for (int o = 16; o > 0; o >>= 1)
        sq += __shfl_down_sync(0xFFFFFFFFu, sq, o);
    if ((t & 31) == 0) partw[t >> 5] = sq;
    __syncthreads();
    if (t == 0) {
        float s = 0.0f;
#pragma unroll
        for (int i = 0; i < 8; i++) s += partw[i];
        d_norms[c] = s;
    }
}

// ---------------------------------------------------------------------------
// k_pdist: 136 upper-tri 32x32 tiles, 512 threads (16 warps).
// 8x8 micro-tile: 64 FFMA per 4 LDS.128. Warp w = d-slice; lane = dh*16+pos.
// Epilogue: shfl-16 dh-fold, 4-round smem tree, sqrt spread over all
// threads. Last CTA writes output and resets cursors/pair/done for replay.
// ---------------------------------------------------------------------------
#define TPAD 36
__global__ void __launch_bounds__(512) k_pdist(float* __restrict__ out) {
    int n = blockIdx.x;
    int bi = 0;
    while (n >= 16 - bi) { n -= 16 - bi; bi++; }
    int bj = bi + n;

    __shared__ __align__(16) float S[2 * 128 * TPAD];   // 9216 floats
    float (*At)[TPAD] = (float (*)[TPAD])S;
    float (*Bt)[TPAD] = (float (*)[TPAD])(S + 128 * TPAD);
    float4* red4 = (float4*)S;
    float*  dots = S + 128 * TPAD;     // overlays Bt (dead by then)
    __shared__ float partw[16];
    __shared__ int   islast;

    int t    = threadIdx.x;
    int w    = t >> 5;
    int lane = t & 31;
    int dh   = lane >> 4;
    int pos  = lane & 15;
    int pi   = pos >> 2;
    int pj   = pos & 3;

    int half = t >> 8;
    int iblk = (t >> 5) & 7;
    int dlo  = t & 31;

    float acc[8][8];
#pragma unroll
    for (int r = 0; r < 8; r++)
#pragma unroll
        for (int c = 0; c < 8; c++) acc[r][c] = 0.0f;

    for (int ck = 0; ck < DIM; ck += 128) {
        __syncthreads();
        {
            int bX = half ? bj : bi;
            float (*T)[TPAD] = half ? Bt : At;
            const float* src = &d_centers[(bX * 32 + iblk * 4) * DIM + ck];
#pragma unroll
            for (int k = 0; k < 4; k++) {
                int dd = dlo + k * 32;
                float4 v;
                v.x = src[0 * DIM + dd];
                v.y = src[1 * DIM + dd];
                v.z = src[2 * DIM + dd];
                v.w = src[3 * DIM + dd];
                *(float4*)&T[dd][iblk * 4] = v;
            }
        }
        __syncthreads();

#pragma unroll
        for (int k = 0; k < 4; k++) {
            int dl = w * 8 + dh + 2 * k;
            float4 a0 = *(float4*)&At[dl][pi * 8];
            float4 a1 = *(float4*)&At[dl][pi * 8 + 4];
            float4 b0 = *(float4*)&Bt[dl][pj * 8];
            float4 b1 = *(float4*)&Bt[dl][pj * 8 + 4];
            float av[8] = {a0.x, a0.y, a0.z, a0.w, a1.x, a1.y, a1.z, a1.w};
            float bv[8] = {b0.x, b0.y, b0.z, b0.w, b1.x, b1.y, b1.z, b1.w};
#pragma unroll
            for (int r = 0; r < 8; r++)
#pragma unroll
                for (int c = 0; c < 8; c++)
                    acc[r][c] += av[r] * bv[c];
        }
    }

#pragma unroll
    for (int r = 0; r < 8; r++)
#pragma unroll
        for (int c = 0; c < 8; c++)
            acc[r][c] += __shfl_down_sync(0xFFFFFFFFu, acc[r][c], 16);

    bool lower = (lane < 16);

#pragma unroll
    for (int span = 8; span >= 1; span >>= 1) {
        __syncthreads();
        if (w >= span && w < 2 * span && lower) {
            int slot = w - span;
#pragma unroll
            for (int r = 0; r < 8; r++)
#pragma unroll
                for (int cq = 0; cq < 2; cq++) {
                    float4 v = make_float4(acc[r][cq*4], acc[r][cq*4+1],
                                           acc[r][cq*4+2], acc[r][cq*4+3]);
                    red4[((slot * 16 + pos) * 17) + r * 2 + cq] = v;
                }
        }
        __syncthreads();
        if (w < span && lower) {
#pragma unroll
            for (int r = 0; r < 8; r++)
#pragma unroll
                for (int cq = 0; cq < 2; cq++) {
                    float4 v = red4[((w * 16 + pos) * 17) + r * 2 + cq];
                    acc[r][cq*4]   += v.x; acc[r][cq*4+1] += v.y;
                    acc[r][cq*4+2] += v.z; acc[r][cq*4+3] += v.w;
                }
        }
    }

    __syncthreads();
    if (w == 0 && lower) {
#pragma unroll
        for (int r = 0; r < 8; r++)
#pragma unroll
            for (int cq = 0; cq < 2; cq++)
                *(float4*)&dots[(pi * 8 + r) * 32 + pj * 8 + cq * 4] =
                    make_float4(acc[r][cq*4], acc[r][cq*4+1],
                                acc[r][cq*4+2], acc[r][cq*4+3]);
    }
    __syncthreads();

    float local = 0.0f;
#pragma unroll
    for (int q = 0; q < 2; q++) {
        int p  = t * 2 + q;
        int i2 = p >> 5;
        int j2 = p & 31;
        int gi = bi * 32 + i2;
        int gj = bj * 32 + j2;
        if (gi < gj) {
            float sq = d_norms[gi] + d_norms[gj] - 2.0f * dots[p];
            local += sqrtf(fmaxf(sq, 1e-12f));
        }
    }

#pragma unroll
    for (int o = 16; o > 0; o >>= 1)
        local += __shfl_down_sync(0xFFFFFFFFu, local, o);
    if (lane == 0) partw[w] = local;
    __syncthreads();
    if (t == 0) {
        float sum = 0.0f;
#pragma unroll
        for (int i = 0; i < 16; i++) sum += partw[i];
        atomicAdd(&d_pair_sum, sum);
        __threadfence();
        islast = (atomicAdd(&d_done, 1) == NTILES - 1) ? 1 : 0;
    }
    __syncthreads();

    if (islast) {
        if (t == 0) {
            __threadfence();
            out[0] = -(*(volatile float*)&d_pair_sum) / (float)NPAIRS;
            d_pair_sum = 0.0f;
            d_done = 0;
        }
        d_cursor[t * CPAD] = 0;   // reset padded cursors for next replay
    }
}

// ---------------------------------------------------------------------------
extern "C" void kernel_launch(void* const* d_in, const int* in_sizes, int n_in,
                              void* d_out, int out_size) {
    const float* matrix = (const float*)d_in[0];
    const int*   label  = (const int*)d_in[1];
    float*       out    = (float*)d_out;

    static bool attr_set = false;
    if (!attr_set) {
        cudaFuncSetAttribute(k_sums, cudaFuncAttributeMaxDynamicSharedMemorySize,
                             SMEM_DYN);
        attr_set = true;
    }

    k_scatter<<<SCTAS, 512>>>(label);
    k_sums<<<CLUSTER, 256, SMEM_DYN>>>(matrix);
    k_pdist<<<NTILES, 512>>>(out);
}

// round 15
// speedup vs baseline: 1.3330x; 1.3330x over previous
#include <cuda_runtime.h>
#include <cstdint>

#define N_ROWS  262144
#define DIM     256
#define CLUSTER 512
#define SLACK   1024
#define NPAIRS  (CLUSTER * (CLUSTER - 1) / 2)   // 130816
#define NTILES  136                             // 16*17/2 upper-tri 32x32 tiles
#define SCTAS   128
#define RPC     (N_ROWS / SCTAS)                // 2048
#define CPAD    32                              // 1 cursor per 128B line

// ---- device scratch (zero-initialized at module load; the LAST k_pdist CTA
//      resets cursors/pair/done so each graph replay sees zeros) ----
__device__ int   d_cursor[CLUSTER * CPAD];         // padded: 1 line per counter
__device__ int   d_perm[CLUSTER * SLACK];          // 2 MB
__device__ float d_centers[CLUSTER * DIM];         // 512 KB (L2-resident)
__device__ float d_norms[CLUSTER];
__device__ float d_pair_sum;
__device__ int   d_done;

__device__ __forceinline__ float4 ldcs4(const float* p) {
    float4 v;
    asm volatile("ld.global.cs.v4.f32 {%0,%1,%2,%3}, [%4];"
                 : "=f"(v.x), "=f"(v.y), "=f"(v.z), "=f"(v.w) : "l"(p));
    return v;
}

// ---------------------------------------------------------------------------
// k_scatter: CTA-aggregated counting scatter (r10 version, measured 7.07us).
// ---------------------------------------------------------------------------
__global__ void __launch_bounds__(512) k_scatter(const int* __restrict__ label) {
    __shared__ int hist[CLUSTER];
    __shared__ int curs[CLUSTER];
    int t  = threadIdx.x;
    int r0 = blockIdx.x * RPC;

    hist[t] = 0;
    __syncthreads();

    int labs[4];
#pragma unroll
    for (int k = 0; k < 4; k++) {
        labs[k] = label[r0 + k * 512 + t];
        atomicAdd(&hist[labs[k]], 1);
    }
    __syncthreads();

    int h = hist[t];
    curs[t] = t * SLACK + ((h > 0) ? atomicAdd(&d_cursor[t * CPAD], h) : 0);
    __syncthreads();

#pragma unroll
    for (int k = 0; k < 4; k++) {
        int pos = atomicAdd(&curs[labs[k]], 1);
        d_perm[pos] = r0 + k * 512 + t;
    }
}

// ---------------------------------------------------------------------------
// k_sums: ONE CTA per cluster, 256 threads (8 warps). Each WARP owns a full
// row: two back-to-back LDG.128 cover the contiguous 1KB row -> one DRAM
// row-activation per matrix row (column-split caused two, from uncorrelated
// CTAs). 4-row unroll = 8 independent LDG.128 in flight per thread.
// ---------------------------------------------------------------------------
__global__ void __launch_bounds__(256) k_sums(const float* __restrict__ matrix) {
    int c    = blockIdx.x;
    int t    = threadIdx.x;
    int lane = t & 31;
    int wp   = t >> 5;            // 8 warps

    int cnt = d_cursor[c * CPAD];
    const int* __restrict__ p = d_perm + c * SLACK;

    __shared__ int    sidx[256];
    __shared__ float4 part0[256];
    __shared__ float4 part1[256];
    __shared__ float  nsum[2];

    float4 a0 = make_float4(0.f, 0.f, 0.f, 0.f);
    float4 a1 = make_float4(0.f, 0.f, 0.f, 0.f);

    for (int base = 0; base < cnt; base += 256) {
        int m = min(256, cnt - base);
        __syncthreads();
        if (t < m) sidx[t] = p[base + t];
        __syncthreads();

        int i = wp;
        for (; i + 24 < m; i += 32) {       // 4 rows per iter, stride 8
            const float* r0 = matrix + (size_t)sidx[i]      * DIM;
            const float* r1 = matrix + (size_t)sidx[i + 8]  * DIM;
            const float* r2 = matrix + (size_t)sidx[i + 16] * DIM;
            const float* r3 = matrix + (size_t)sidx[i + 24] * DIM;
            // low half (cols 0..127) + high half (cols 128..255), contiguous 1KB per row
            float4 v0 = ldcs4(r0 + lane * 4), w0 = ldcs4(r0 + 128 + lane * 4);
            float4 v1 = ldcs4(r1 + lane * 4), w1 = ldcs4(r1 + 128 + lane * 4);
            float4 v2 = ldcs4(r2 + lane * 4), w2 = ldcs4(r2 + 128 + lane * 4);
            float4 v3 = ldcs4(r3 + lane * 4), w3 = ldcs4(r3 + 128 + lane * 4);
            float4 sA, sB;
            sA.x = v0.x + v1.x; sA.y = v0.y + v1.y; sA.z = v0.z + v1.z; sA.w = v0.w + v1.w;
            sB.x = v2.x + v3.x; sB.y = v2.y + v3.y; sB.z = v2.z + v3.z; sB.w = v2.w + v3.w;
            a0.x += sA.x + sB.x; a0.y += sA.y + sB.y;
            a0.z += sA.z + sB.z; a0.w += sA.w + sB.w;
            sA.x = w0.x + w1.x; sA.y = w0.y + w1.y; sA.z = w0.z + w1.z; sA.w = w0.w + w1.w;
            sB.x = w2.x + w3.x; sB.y = w2.y + w3.y; sB.z = w2.z + w3.z; sB.w = w2.w + w3.w;
            a1.x += sA.x + sB.x; a1.y += sA.y + sB.y;
            a1.z += sA.z + sB.z; a1.w += sA.w + sB.w;
        }
        for (; i < m; i += 8) {             // tail rows for this warp
            const float* r0 = matrix + (size_t)sidx[i] * DIM;
            float4 v = ldcs4(r0 + lane * 4), w = ldcs4(r0 + 128 + lane * 4);
            a0.x += v.x; a0.y += v.y; a0.z += v.z; a0.w += v.w;
            a1.x += w.x; a1.y += w.y; a1.z += w.z; a1.w += w.w;
        }
    }

    part0[t] = a0;
    part1[t] = a1;
    __syncthreads();

    // threads 0..31: cols lane*4 (low half); threads 32..63: cols 128+lane*4
    if (t < 64) {
        int l = t & 31;
        const float4* P = (t < 32) ? part0 : part1;
        float4 cen = make_float4(0.f, 0.f, 0.f, 0.f);
#pragma unroll
        for (int k = 0; k < 8; k++) {
            float4 v = P[l + k * 32];
            cen.x += v.x; cen.y += v.y; cen.z += v.z; cen.w += v.w;
        }
        float inv = 1.0f / fmaxf((float)cnt, 1.0f);
        cen.x *= inv; cen.y *= inv; cen.z *= inv; cen.w *= inv;
        int colbase = (t < 32) ? l * 4 : 128 + l * 4;
        *(float4*)&d_centers[c * DIM + colbase] = cen;

        float sq = cen.x * cen.x + cen.y * cen.y + cen.z * cen.z + cen.w * cen.w;
#pragma unroll
        for (int o = 16; o > 0; o >>= 1)
            sq += __shfl_down_sync(0xFFFFFFFFu, sq, o);
        if (l == 0) nsum[t >> 5] = sq;
    }
    __syncthreads();
    if (t == 0) d_norms[c] = nsum[0] + nsum[1];
}

// ---------------------------------------------------------------------------
// k_pdist: 136 upper-tri 32x32 tiles, 512 threads (16 warps).
// 8x8 micro-tile: 64 FFMA per 4 LDS.128. Warp w = d-slice; lane = dh*16+pos.
// Epilogue: shfl-16 dh-fold, 4-round smem tree, sqrt spread over all
// threads. Last CTA writes output and resets cursors/pair/done for replay.
// ---------------------------------------------------------------------------
#define TPAD 36
__global__ void __launch_bounds__(512) k_pdist(float* __restrict__ out) {
    int n = blockIdx.x;
    int bi = 0;
    while (n >= 16 - bi) { n -= 16 - bi; bi++; }
    int bj = bi + n;

    __shared__ __align__(16) float S[2 * 128 * TPAD];   // 9216 floats
    float (*At)[TPAD] = (float (*)[TPAD])S;
    float (*Bt)[TPAD] = (float (*)[TPAD])(S + 128 * TPAD);
    float4* red4 = (float4*)S;
    float*  dots = S + 128 * TPAD;     // overlays Bt (dead by then)
    __shared__ float partw[16];
    __shared__ int   islast;

    int t    = threadIdx.x;
    int w    = t >> 5;
    int lane = t & 31;
    int dh   = lane >> 4;
    int pos  = lane & 15;
    int pi   = pos >> 2;
    int pj   = pos & 3;

    int half = t >> 8;
    int iblk = (t >> 5) & 7;
    int dlo  = t & 31;

    float acc[8][8];
#pragma unroll
    for (int r = 0; r < 8; r++)
#pragma unroll
        for (int c = 0; c < 8; c++) acc[r][c] = 0.0f;

    for (int ck = 0; ck < DIM; ck += 128) {
        __syncthreads();
        {
            int bX = half ? bj : bi;
            float (*T)[TPAD] = half ? Bt : At;
            const float* src = &d_centers[(bX * 32 + iblk * 4) * DIM + ck];
#pragma unroll
            for (int k = 0; k < 4; k++) {
                int dd = dlo + k * 32;
                float4 v;
                v.x = src[0 * DIM + dd];
                v.y = src[1 * DIM + dd];
                v.z = src[2 * DIM + dd];
                v.w = src[3 * DIM + dd];
                *(float4*)&T[dd][iblk * 4] = v;
            }
        }
        __syncthreads();

#pragma unroll
        for (int k = 0; k < 4; k++) {
            int dl = w * 8 + dh + 2 * k;
            float4 a0 = *(float4*)&At[dl][pi * 8];
            float4 a1 = *(float4*)&At[dl][pi * 8 + 4];
            float4 b0 = *(float4*)&Bt[dl][pj * 8];
            float4 b1 = *(float4*)&Bt[dl][pj * 8 + 4];
            float av[8] = {a0.x, a0.y, a0.z, a0.w, a1.x, a1.y, a1.z, a1.w};
            float bv[8] = {b0.x, b0.y, b0.z, b0.w, b1.x, b1.y, b1.z, b1.w};
#pragma unroll
            for (int r = 0; r < 8; r++)
#pragma unroll
                for (int c = 0; c < 8; c++)
                    acc[r][c] += av[r] * bv[c];
        }
    }

#pragma unroll
    for (int r = 0; r < 8; r++)
#pragma unroll
        for (int c = 0; c < 8; c++)
            acc[r][c] += __shfl_down_sync(0xFFFFFFFFu, acc[r][c], 16);

    bool lower = (lane < 16);

#pragma unroll
    for (int span = 8; span >= 1; span >>= 1) {
        __syncthreads();
        if (w >= span && w < 2 * span && lower) {
            int slot = w - span;
#pragma unroll
            for (int r = 0; r < 8; r++)
#pragma unroll
                for (int cq = 0; cq < 2; cq++) {
                    float4 v = make_float4(acc[r][cq*4], acc[r][cq*4+1],
                                           acc[r][cq*4+2], acc[r][cq*4+3]);
                    red4[((slot * 16 + pos) * 17) + r * 2 + cq] = v;
                }
        }
        __syncthreads();
        if (w < span && lower) {
#pragma unroll
            for (int r = 0; r < 8; r++)
#pragma unroll
                for (int cq = 0; cq < 2; cq++) {
                    float4 v = red4[((w * 16 + pos) * 17) + r * 2 + cq];
                    acc[r][cq*4]   += v.x; acc[r][cq*4+1] += v.y;
                    acc[r][cq*4+2] += v.z; acc[r][cq*4+3] += v.w;
                }
        }
    }

    __syncthreads();
    if (w == 0 && lower) {
#pragma unroll
        for (int r = 0; r < 8; r++)
#pragma unroll
            for (int cq = 0; cq < 2; cq++)
                *(float4*)&dots[(pi * 8 + r) * 32 + pj * 8 + cq * 4] =
                    make_float4(acc[r][cq*4], acc[r][cq*4+1],
                                acc[r][cq*4+2], acc[r][cq*4+3]);
    }
    __syncthreads();

    float local = 0.0f;
#pragma unroll
    for (int q = 0; q < 2; q++) {
        int p  = t * 2 + q;
        int i2 = p >> 5;
        int j2 = p & 31;
        int gi = bi * 32 + i2;
        int gj = bj * 32 + j2;
        if (gi < gj) {
            float sq = d_norms[gi] + d_norms[gj] - 2.0f * dots[p];
            local += sqrtf(fmaxf(sq, 1e-12f));
        }
    }

#pragma unroll
    for (int o = 16; o > 0; o >>= 1)
        local += __shfl_down_sync(0xFFFFFFFFu, local, o);
    if (lane == 0) partw[w] = local;
    __syncthreads();
    if (t == 0) {
        float sum = 0.0f;
#pragma unroll
        for (int i = 0; i < 16; i++) sum += partw[i];
        atomicAdd(&d_pair_sum, sum);
        __threadfence();
        islast = (atomicAdd(&d_done, 1) == NTILES - 1) ? 1 : 0;
    }
    __syncthreads();

    if (islast) {
        if (t == 0) {
            __threadfence();
            out[0] = -(*(volatile float*)&d_pair_sum) / (float)NPAIRS;
            d_pair_sum = 0.0f;
            d_done = 0;
        }
        d_cursor[t * CPAD] = 0;   // reset padded cursors for next replay
    }
}

// ---------------------------------------------------------------------------
extern "C" void kernel_launch(void* const* d_in, const int* in_sizes, int n_in,
                              void* d_out, int out_size) {
    const float* matrix = (const float*)d_in[0];
    const int*   label  = (const int*)d_in[1];
    float*       out    = (float*)d_out;

    k_scatter<<<SCTAS, 512>>>(label);
    k_sums<<<CLUSTER, 256>>>(matrix);
    k_pdist<<<NTILES, 512>>>(out);
}

// round 16
// speedup vs baseline: 1.4757x; 1.1071x over previous
#include <cuda_runtime.h>
#include <cstdint>

#define N_ROWS  262144
#define DIM     256
#define CLUSTER 512
#define SLACK   1024
#define NPAIRS  (CLUSTER * (CLUSTER - 1) / 2)   // 130816
#define NTILES  136                             // 16*17/2 upper-tri 32x32 tiles
#define SCTAS   128
#define RPC     (N_ROWS / SCTAS)                // 2048

// ---- device scratch (zero-initialized at module load; the LAST k_pdist CTA
//      resets cursors/norms/pair/done so each graph replay sees zeros) ----
__device__ int   d_cursor[CLUSTER];
__device__ int   d_perm[CLUSTER * SLACK];          // 2 MB
__device__ float d_centers[CLUSTER * DIM];         // 512 KB (L2-resident)
__device__ float d_norms[CLUSTER];
__device__ float d_pair_sum;
__device__ int   d_done;

__device__ __forceinline__ float4 ldcs4(const float* p) {
    float4 v;
    asm volatile("ld.global.cs.v4.f32 {%0,%1,%2,%3}, [%4];"
                 : "=f"(v.x), "=f"(v.y), "=f"(v.z), "=f"(v.w) : "l"(p));
    return v;
}

// ---------------------------------------------------------------------------
// k_scatter: CTA-aggregated counting scatter (measured-best family, ~7us).
// Zero-based global cursors; cluster base t*SLACK folded into smem cursors.
// ---------------------------------------------------------------------------
__global__ void __launch_bounds__(512) k_scatter(const int* __restrict__ label) {
    __shared__ int hist[CLUSTER];
    __shared__ int curs[CLUSTER];
    int t  = threadIdx.x;
    int r0 = blockIdx.x * RPC;

    hist[t] = 0;
    __syncthreads();

    int labs[4];
#pragma unroll
    for (int k = 0; k < 4; k++) {
        labs[k] = label[r0 + k * 512 + t];
        atomicAdd(&hist[labs[k]], 1);
    }
    __syncthreads();

    int h = hist[t];
    curs[t] = t * SLACK + ((h > 0) ? atomicAdd(&d_cursor[t], h) : 0);
    __syncthreads();

#pragma unroll
    for (int k = 0; k < 4; k++) {
        int pos = atomicAdd(&curs[labs[k]], 1);
        d_perm[pos] = r0 + k * 512 + t;
    }
}

// ---------------------------------------------------------------------------
// k_sums: 2 CTAs per cluster (128-column halves), 256 threads =
// 32 column-groups (float4) x 8 row-slots. Each thread keeps 8 independent
// LDG.128 in flight (explicit v[8] batch + add tree). Measured at the
// practical HBM roofline for this access pattern. FROZEN.
// ---------------------------------------------------------------------------
__global__ void __launch_bounds__(256) k_sums(const float* __restrict__ matrix) {
    int bx = blockIdx.x;
    int c  = bx >> 1;
    int hc = bx & 1;
    int t  = threadIdx.x;
    int cg = t & 31;
    int s  = t >> 5;
    int colbase = hc * 128 + cg * 4;

    int cnt = d_cursor[c];
    const int* __restrict__ p = d_perm + c * SLACK;

    __shared__ int    sidx[256];
    __shared__ float4 part[256];

    float4 acc = make_float4(0.f, 0.f, 0.f, 0.f);

    int base = 0;
    for (; base + 256 <= cnt; base += 256) {
        __syncthreads();
        sidx[t] = p[base + t];
        __syncthreads();
        for (int r = 0; r < 32; r += 8) {
            float4 v[8];
#pragma unroll
            for (int u = 0; u < 8; u++) {
                int row = sidx[(r + u) * 8 + s];
                v[u] = ldcs4(&matrix[(size_t)row * DIM + colbase]);
            }
            float4 s01, s23, s45, s67, sA, sB;
            s01.x = v[0].x + v[1].x; s01.y = v[0].y + v[1].y; s01.z = v[0].z + v[1].z; s01.w = v[0].w + v[1].w;
            s23.x = v[2].x + v[3].x; s23.y = v[2].y + v[3].y; s23.z = v[2].z + v[3].z; s23.w = v[2].w + v[3].w;
            s45.x = v[4].x + v[5].x; s45.y = v[4].y + v[5].y; s45.z = v[4].z + v[5].z; s45.w = v[4].w + v[5].w;
            s67.x = v[6].x + v[7].x; s67.y = v[6].y + v[7].y; s67.z = v[6].z + v[7].z; s67.w = v[6].w + v[7].w;
            sA.x = s01.x + s23.x; sA.y = s01.y + s23.y; sA.z = s01.z + s23.z; sA.w = s01.w + s23.w;
            sB.x = s45.x + s67.x; sB.y = s45.y + s67.y; sB.z = s45.z + s67.z; sB.w = s45.w + s67.w;
            acc.x += sA.x + sB.x; acc.y += sA.y + sB.y;
            acc.z += sA.z + sB.z; acc.w += sA.w + sB.w;
        }
    }
    {   // tail
        int m = cnt - base;
        __syncthreads();
        if (t < m) sidx[t] = p[base + t];
        __syncthreads();
        for (int r = s; r < m; r += 8) {
            int row = sidx[r];
            float4 v = ldcs4(&matrix[(size_t)row * DIM + colbase]);
            acc.x += v.x; acc.y += v.y; acc.z += v.z; acc.w += v.w;
        }
    }

    part[t] = acc;
    __syncthreads();

    if (t < 32) {
        float4 cen = make_float4(0.f, 0.f, 0.f, 0.f);
#pragma unroll
        for (int k = 0; k < 8; k++) {
            float4 a = part[t + k * 32];
            cen.x += a.x; cen.y += a.y; cen.z += a.z; cen.w += a.w;
        }
        float inv = 1.0f / fmaxf((float)cnt, 1.0f);
        cen.x *= inv; cen.y *= inv; cen.z *= inv; cen.w *= inv;
        *(float4*)&d_centers[c * DIM + hc * 128 + t * 4] = cen;

        float nrm = cen.x * cen.x + cen.y * cen.y + cen.z * cen.z + cen.w * cen.w;
#pragma unroll
        for (int o = 16; o > 0; o >>= 1)
            nrm += __shfl_down_sync(0xFFFFFFFFu, nrm, o);
        if (t == 0) atomicAdd(&d_norms[c], nrm);
    }
}

// ---------------------------------------------------------------------------
// k_pdist: 136 upper-tri 32x32 tiles, 1024 threads (32 warps, occ 50%) —
// the exact version from the 55.8us best run. Transposed smem tiles
// T[d][i] (TPAD=36); 16 d-slices x 64 positions; per d: 2 broadcast
// conflict-free LDS.128 feed 16 FFMA (4x4 micro-tile). Two-wave slice
// reduction through smem (stride 17). Last CTA writes the output and
// resets all device state for the next graph replay.
// ---------------------------------------------------------------------------
#define TPAD 36
__global__ void __launch_bounds__(1024) k_pdist(float* __restrict__ out) {
    // decode upper-tri tile index -> (bi, bj), bi <= bj
    int n = blockIdx.x;
    int bi = 0;
    while (n >= 16 - bi) { n -= 16 - bi; bi++; }
    int bj = bi + n;

    __shared__ __align__(16) float S[2 * 128 * TPAD];   // 36864 B
    float (*At)[TPAD] = (float (*)[TPAD])S;
    float (*Bt)[TPAD] = (float (*)[TPAD])(S + 128 * TPAD);
    __shared__ float partw[32];
    __shared__ int   islast;

    int t  = threadIdx.x;
    int tt = t & 63;          // micro-tile position
    int ds = t >> 6;          // d-slice 0..15
    int ti = tt >> 3;         // i block 0..7
    int tj = tt & 7;          // j block 0..7

    // loader mapping: 1024 threads, one chunk of 128 dims per phase
    int half = t >> 9;        // 0 -> A, 1 -> B
    int iblk = (t >> 6) & 7;  // i block 0..7
    int dlo  = t & 63;        // d lane 0..63 (k adds 64)

    float acc[4][4];
#pragma unroll
    for (int a = 0; a < 4; a++)
#pragma unroll
        for (int b = 0; b < 4; b++) acc[a][b] = 0.0f;

    for (int ck = 0; ck < DIM; ck += 128) {
        __syncthreads();
        {
            int bX = half ? bj : bi;
            float (*T)[TPAD] = half ? Bt : At;
            const float* src = &d_centers[(bX * 32 + iblk * 4) * DIM + ck];
#pragma unroll
            for (int k = 0; k < 2; k++) {
                int dd = dlo + k * 64;
                float4 v;
                v.x = src[0 * DIM + dd];
                v.y = src[1 * DIM + dd];
                v.z = src[2 * DIM + dd];
                v.w = src[3 * DIM + dd];
                *(float4*)&T[dd][iblk * 4] = v;
            }
        }
        __syncthreads();

        // slice ds covers local rows [ds*8, ds*8+8)
#pragma unroll
        for (int k = 0; k < 8; k++) {
            int dl = ds * 8 + k;
            float4 aV = *(float4*)&At[dl][ti * 4];
            float4 bV = *(float4*)&Bt[dl][tj * 4];
            acc[0][0] += aV.x * bV.x; acc[0][1] += aV.x * bV.y;
            acc[0][2] += aV.x * bV.z; acc[0][3] += aV.x * bV.w;
            acc[1][0] += aV.y * bV.x; acc[1][1] += aV.y * bV.y;
            acc[1][2] += aV.y * bV.z; acc[1][3] += aV.y * bV.w;
            acc[2][0] += aV.z * bV.x; acc[2][1] += aV.z * bV.y;
            acc[2][2] += aV.z * bV.z; acc[2][3] += aV.z * bV.w;
            acc[3][0] += aV.w * bV.x; acc[3][1] += aV.w * bV.y;
            acc[3][2] += aV.w * bV.z; acc[3][3] += aV.w * bV.w;
        }
    }

    // two-wave slice reduction: red[(sl*64+tt)*17 + e], sl = ds mod 8
    __syncthreads();
    float* red = S;           // needs 8*64*17 = 8704 floats <= 9216
    if (ds < 8) {
#pragma unroll
        for (int a = 0; a < 4; a++)
#pragma unroll
            for (int b = 0; b < 4; b++)
                red[((ds)*64 + tt) * 17 + a * 4 + b] = acc[a][b];
    }
    __syncthreads();
    if (ds >= 8) {
#pragma unroll
        for (int a = 0; a < 4; a++)
#pragma unroll
            for (int b = 0; b < 4; b++)
                red[((ds - 8) * 64 + tt) * 17 + a * 4 + b] += acc[a][b];
    }
    __syncthreads();

    // gather: one pair per thread
    float local = 0.0f;
    {
        int pp  = t;              // pair 0..1023
        int tt2 = pp >> 4;
        int e   = pp & 15;
        float dot = 0.0f;
#pragma unroll
        for (int sl = 0; sl < 8; sl++)
            dot += red[(sl * 64 + tt2) * 17 + e];
        int i2 = (tt2 >> 3) * 4 + (e >> 2);
        int j2 = (tt2 & 7) * 4 + (e & 3);
        int gi = bi * 32 + i2;
        int gj = bj * 32 + j2;
        if (gi < gj) {
            float sq = d_norms[gi] + d_norms[gj] - 2.0f * dot;
            local += sqrtf(fmaxf(sq, 1e-12f));
        }
    }

#pragma unroll
    for (int o = 16; o > 0; o >>= 1)
        local += __shfl_down_sync(0xFFFFFFFFu, local, o);
    if ((t & 31) == 0) partw[t >> 5] = local;
    __syncthreads();
    if (t == 0) {
        float sum = 0.0f;
#pragma unroll
        for (int i = 0; i < 32; i++) sum += partw[i];
        atomicAdd(&d_pair_sum, sum);
        __threadfence();
        islast = (atomicAdd(&d_done, 1) == NTILES - 1) ? 1 : 0;
    }
    __syncthreads();

    // last CTA: emit output, then reset all device state for the next replay
    if (islast) {
        if (t == 0) {
            __threadfence();
            out[0] = -(*(volatile float*)&d_pair_sum) / (float)NPAIRS;
            d_pair_sum = 0.0f;
            d_done = 0;
        }
        if (t < CLUSTER) {
            d_cursor[t] = 0;
            d_norms[t]  = 0.0f;
        }
    }
}

// ---------------------------------------------------------------------------
extern "C" void kernel_launch(void* const* d_in, const int* in_sizes, int n_in,
                              void* d_out, int out_size) {
    const float* matrix = (const float*)d_in[0];
    const int*   label  = (const int*)d_in[1];
    float*       out    = (float*)d_out;

    k_scatter<<<SCTAS, 512>>>(label);
    k_sums<<<CLUSTER * 2, 256>>>(matrix);
    k_pdist<<<NTILES, 1024>>>(out);
}